// round 17
// baseline (speedup 1.0000x reference)
#include <cuda_runtime.h>
#include <cuda_fp16.h>
#include <stdint.h>
#include <math.h>

#define H_   12
#define T_   512
#define D_   64
#define C_   768
#define B_   32
#define NQKV_ 2304
#define BT_  16384
#define BHTD_ ((size_t)B_*H_*T_*D_)
#define QSCALE 0.125f

// ------------- device-global scratch (no runtime alloc allowed) -------------
// hi-only granule: 8B = [h(k),h(k+1),h(k+8),h(k+9)] fp16; row = 48 groups x 32B
__device__ __align__(16) uint8_t g_xh[(size_t)BT_*1536];
__device__ __align__(16) uint8_t g_wqh[(size_t)NQKV_*1536];
__device__ __align__(16) uint8_t g_oh[(size_t)BT_*1536];
__device__ __align__(16) uint8_t g_wch[(size_t)C_*1536];
__device__ __align__(16) __half g_qhi[BHTD_];
__device__ __align__(16) __half g_khi[BHTD_];
__device__ __align__(16) __half g_vhi[BHTD_];
__device__ __align__(16) __half g_vthi[BHTD_];   // [b,h,d,s]
__device__ __align__(16) float g_wcomb[C_*C_];
__device__ __align__(16) float g_bcomb[C_];

// ------------------------------ helpers -------------------------------------
__device__ __forceinline__ uint32_t smem_u32(const void* p) {
    uint32_t a;
    asm("{ .reg .u64 t; cvta.to.shared.u64 t, %1; cvt.u32.u64 %0, t; }"
        : "=r"(a) : "l"(p));
    return a;
}
__device__ __forceinline__ void mma_f16(float* c, const uint32_t* a,
                                        uint32_t b0, uint32_t b1) {
    asm volatile(
        "mma.sync.aligned.m16n8k16.row.col.f32.f16.f16.f32 "
        "{%0,%1,%2,%3}, {%4,%5,%6,%7}, {%8,%9}, {%0,%1,%2,%3};"
        : "+f"(c[0]), "+f"(c[1]), "+f"(c[2]), "+f"(c[3])
        : "r"(a[0]), "r"(a[1]), "r"(a[2]), "r"(a[3]), "r"(b0), "r"(b1));
}
__device__ __forceinline__ uint32_t lds32(uint32_t a) {
    uint32_t v;
    asm volatile("ld.shared.b32 %0, [%1];" : "=r"(v) : "r"(a));
    return v;
}
__device__ __forceinline__ void lds64(uint32_t a, uint32_t& x, uint32_t& y) {
    asm volatile("ld.shared.v2.b32 {%0,%1}, [%2];" : "=r"(x), "=r"(y) : "r"(a));
}
__device__ __forceinline__ uint32_t pack2h(float a, float b) {
    __half2 t = __floats2half2_rn(a, b);
    return *(uint32_t*)&t;
}
// 8B hi-only granule from 4 fp32 (k, k+1, k+8, k+9)
__device__ __forceinline__ void pack_g8(float f0, float f1, float f2, float f3,
                                        uint32_t* w) {
    w[0] = pack2h(f0, f1);
    w[1] = pack2h(f2, f3);
}

// ------------------------------ prep kernels --------------------------------
__global__ void __launch_bounds__(256) k_prep_xh(const float* __restrict__ x) {
    int gid = blockIdx.x * 256 + threadIdx.x;     // BT*192 sub-granules
    int lc = gid & 3, g = (gid >> 2) % 48;
    int m = gid / 192;
    const float* xr = x + (size_t)m * 768 + g * 16 + lc * 2;
    uint32_t w[2];
    pack_g8(xr[0], xr[1], xr[8], xr[9], w);
    *(uint2*)(g_xh + (size_t)m * 1536 + g * 32 + lc * 8) = *(uint2*)w;
}

__global__ void __launch_bounds__(256) k_prep_wqh(const float* __restrict__ W) {
    int gid = blockIdx.x * 256 + threadIdx.x;
    int lc = gid & 3, g = (gid >> 2) % 48;
    int n = gid / 192;
    int h = n / 192, j = n % 192;
    const float* wb = W + ((size_t)h * 768 + g * 16 + lc * 2) * 192 + j;
    uint32_t w[2];
    pack_g8(wb[0], wb[192], wb[8*192], wb[9*192], w);
    *(uint2*)(g_wqh + (size_t)n * 1536 + g * 32 + lc * 8) = *(uint2*)w;
}

__global__ void __launch_bounds__(256) k_prep_wch() {
    int gid = blockIdx.x * 256 + threadIdx.x;
    int lc = gid & 3, g = (gid >> 2) % 48;
    int n = gid / 192;
    int k0 = g * 16 + lc * 2;
    uint32_t w[2];
    pack_g8(g_wcomb[(size_t)k0*768 + n],     g_wcomb[(size_t)(k0+1)*768 + n],
            g_wcomb[(size_t)(k0+8)*768 + n], g_wcomb[(size_t)(k0+9)*768 + n], w);
    *(uint2*)(g_wch + (size_t)n * 1536 + g * 32 + lc * 8) = *(uint2*)w;
}

// zero g_wcomb + init g_bcomb = bproj
__global__ void __launch_bounds__(256) k_binit(const float* __restrict__ bproj) {
    int idx = blockIdx.x * 256 + threadIdx.x;
    if (idx < C_*C_) g_wcomb[idx] = 0.0f;
    int j = idx - C_*C_;
    if (j >= 0 && j < C_) g_bcomb[j] = bproj[j];
}

__global__ void __launch_bounds__(256) k_bcomb(const float* __restrict__ bph,
                                               const float* __restrict__ Wproj) {
    int r0 = blockIdx.x * 32;
    int t = threadIdx.x;
    float a0 = 0.f, a1 = 0.f, a2 = 0.f;
    for (int rr = 0; rr < 32; ++rr) {
        int r = r0 + rr;
        float bv = bph[r];
        const float* wr = Wproj + (size_t)r * C_;
        a0 = fmaf(bv, wr[t],       a0);
        a1 = fmaf(bv, wr[t + 256], a1);
        a2 = fmaf(bv, wr[t + 512], a2);
    }
    atomicAdd(&g_bcomb[t],       a0);
    atomicAdd(&g_bcomb[t + 256], a1);
    atomicAdd(&g_bcomb[t + 512], a2);
}

// ------- Wcomb precompute: fp32, 4-way K-split, atomic accumulate -----------
__global__ void __launch_bounds__(256) sgemm64ks(
    const float* __restrict__ A, const float* __restrict__ Bm,
    float* __restrict__ Cm)
{
    __shared__ float As[16][68];
    __shared__ float Bs[16][68];
    const int z = blockIdx.z;
    const float* Ab = A  + (size_t)z * 64 * C_;
    const float* Bb = Bm + (size_t)z * C_ * C_;
    float*       Cb = Cm + (size_t)z * 64 * C_;
    const int tid = threadIdx.x;
    const int tx = tid % 16, ty = tid / 16;
    const int n0 = blockIdx.y * 64;
    const int kbeg = blockIdx.x * 192, kend = kbeg + 192;
    float acc[4][4] = {};
    for (int kt = kbeg; kt < kend; kt += 16) {
        {
            int m = tid / 4, kq = (tid % 4) * 4;
            float4 v = *(const float4*)(Ab + (size_t)m*C_ + kt + kq);
            As[kq+0][m] = v.x; As[kq+1][m] = v.y; As[kq+2][m] = v.z; As[kq+3][m] = v.w;
        }
        {
            int kk = tid / 16, nn = (tid % 16) * 4;
            *(float4*)&Bs[kk][nn] = *(const float4*)(Bb + (size_t)(kt+kk)*C_ + n0 + nn);
        }
        __syncthreads();
        #pragma unroll
        for (int k = 0; k < 16; ++k) {
            float a[4], b[4];
            #pragma unroll
            for (int i = 0; i < 4; ++i) a[i] = As[k][ty*4+i];
            *(float4*)b = *(const float4*)&Bs[k][tx*4];
            #pragma unroll
            for (int i = 0; i < 4; ++i)
                #pragma unroll
                for (int j = 0; j < 4; ++j)
                    acc[i][j] = fmaf(a[i], b[j], acc[i][j]);
        }
        __syncthreads();
    }
    #pragma unroll
    for (int i = 0; i < 4; ++i) {
        int m = ty*4 + i;
        #pragma unroll
        for (int j = 0; j < 4; ++j)
            atomicAdd(&Cb[(size_t)m*C_ + n0 + tx*4 + j], acc[i][j]);
    }
}

// ---- HMMA fp16 single-term GEMM, 128x128 CTA, 64x64 warp tile, 4 warps ----
// A/B hi-only 8B granules; rows 64B/chunk + 32B XOR swizzle on (row&2).
// 16B cp.async; 3-stage pipeline, lookahead 2 via wait_group 1.
// 64x64 warp tile: A and B each amortize to 2B/thread/MMA (symmetric reuse).
#define RSTR 64
#define ATILE (128*RSTR)      // 8192
#define BTILE (128*RSTR)      // 8192
#define GSTAGE (ATILE+BTILE)  // 16384
#define HM_SMEM (3*GSTAGE)    // 49152

template<int EPI>
__global__ void __launch_bounds__(128, 3) hmma_gemm(
    const uint8_t* __restrict__ Ac, const uint8_t* __restrict__ Bc,
    float* __restrict__ Cout, const float* __restrict__ bias)
{
    extern __shared__ char smem[];
    const uint32_t sbase = smem_u32(smem);
    const int tid = threadIdx.x;
    const int wid = tid >> 5, ln = tid & 31;
    const int n0 = blockIdx.x * 128, m0 = blockIdx.y * 128;
    const int wm = wid & 1, wn = wid >> 1;      // 2 x 2 warp grid
    const int mrow = wm * 64, ncol = wn * 64;
    const int lr = ln >> 2, lc = ln & 3;
    const int lrb = (lr >> 1) & 1;

    const uint8_t* gA = Ac + (size_t)m0 * 1536;
    const uint8_t* gB = Bc + (size_t)n0 * 1536;

    auto load_chunk = [&](int kc, int stage) {
        uint32_t sb = sbase + (uint32_t)stage * GSTAGE;
        const uint8_t* pA = gA + kc * 64;       // contiguous 64B per row-chunk
        #pragma unroll
        for (int i = 0; i < 4; ++i) {
            int gid = tid + i * 128;            // 0..511 : 128 rows x 4 x16B
            int r = gid >> 2, c2 = gid & 3;
            uint32_t doff = (uint32_t)(c2*16) ^ (uint32_t)((r & 2) << 4);
            asm volatile("cp.async.ca.shared.global [%0], [%1], 16;"
                :: "r"(sb + r*RSTR + doff), "l"(pA + (size_t)r*1536 + c2*16));
        }
        const uint8_t* pB = gB + kc * 64;
        uint32_t bb = sb + ATILE;
        #pragma unroll
        for (int i = 0; i < 4; ++i) {
            int gid = tid + i * 128;
            int r = gid >> 2, c2 = gid & 3;
            uint32_t doff = (uint32_t)(c2*16) ^ (uint32_t)((r & 2) << 4);
            asm volatile("cp.async.ca.shared.global [%0], [%1], 16;"
                :: "r"(bb + r*RSTR + doff), "l"(pB + (size_t)r*1536 + c2*16));
        }
        asm volatile("cp.async.commit_group;");
    };

    float acc[4][8][4] = {};
    load_chunk(0, 0);
    load_chunk(1, 1);
    int sc = 0, sn = 2;
    for (int c = 0; c < 24; ++c) {
        if (c < 23) { asm volatile("cp.async.wait_group 1;"); }
        else        { asm volatile("cp.async.wait_group 0;"); }
        __syncthreads();            // all warps see chunk c; stage sn free
        if (c + 2 < 24) load_chunk(c + 2, sn);

        uint32_t sA = sbase + (uint32_t)sc * GSTAGE;
        uint32_t aBr = sA + (uint32_t)((mrow + lr)*RSTR + lc*8);
        uint32_t bBr = sA + ATILE + (uint32_t)((ncol + lr)*RSTR + lc*8);

        #pragma unroll
        for (int ks = 0; ks < 2; ++ks) {
            const uint32_t ksB = (uint32_t)((ks ^ lrb) * 32);
            uint32_t aF[4][4];
            #pragma unroll
            for (int mt = 0; mt < 4; ++mt) {
                uint32_t base = aBr + mt*16*RSTR + ksB;
                lds64(base,          aF[mt][0], aF[mt][2]);
                lds64(base + 8*RSTR, aF[mt][1], aF[mt][3]);
            }
            #pragma unroll
            for (int nt = 0; nt < 8; ++nt) {
                uint32_t b0, b1;
                lds64(bBr + nt*8*RSTR + ksB, b0, b1);
                #pragma unroll
                for (int mt = 0; mt < 4; ++mt)
                    mma_f16(acc[mt][nt], aF[mt], b0, b1);
            }
        }
        sc = (sc == 2) ? 0 : sc + 1;
        sn = (sn == 2) ? 0 : sn + 1;
        // no trailing sync: next iteration's barrier protects buffer reuse
    }

    // ------------------------------- epilogue --------------------------------
    if (EPI == 0) {
        #pragma unroll
        for (int mt = 0; mt < 4; ++mt) {
            int m = m0 + mrow + mt*16 + lr;
            #pragma unroll
            for (int nt = 0; nt < 8; ++nt) {
                int n = n0 + ncol + nt*8 + lc*2;
                float b0 = bias[n], b1 = bias[n+1];
                float* ac = acc[mt][nt];
                float2 v0 = {ac[0] + b0, ac[1] + b1};
                float2 v1 = {ac[2] + b0, ac[3] + b1};
                *(float2*)(Cout + (size_t)m * C_ + n) = v0;
                *(float2*)(Cout + (size_t)(m+8) * C_ + n) = v1;
            }
        }
    } else {
        const int nbase = n0 + ncol;                 // 64-aligned, single blk
        const int h = nbase / 192, rbase = nbase % 192;
        const int blk = rbase >> 6;
        __half* dst = (blk == 0) ? g_qhi : ((blk == 1) ? g_khi : g_vhi);
        const float sc2 = (blk == 0) ? QSCALE : 1.0f;
        #pragma unroll
        for (int mt = 0; mt < 4; ++mt) {
            #pragma unroll
            for (int rr = 0; rr < 2; ++rr) {
                int mm = m0 + mrow + mt*16 + lr + rr*8;
                int b_ = mm >> 9, t_ = mm & 511;
                size_t obase = (((size_t)b_ * H_ + h) * T_ + t_) * 64;
                #pragma unroll
                for (int nt = 0; nt < 8; ++nt) {
                    int n = nbase + nt*8 + lc*2;
                    size_t o = obase + nt*8 + lc*2;
                    float v0 = (acc[mt][nt][rr*2+0] + bias[n])   * sc2;
                    float v1 = (acc[mt][nt][rr*2+1] + bias[n+1]) * sc2;
                    *(__half2*)(dst + o) = __floats2half2_rn(v0, v1);
                }
            }
        }
    }
}

// ------------------------ V transpose: [s][d] -> [d][s] ----------------------
__global__ void __launch_bounds__(256) k_vT() {
    __shared__ __half thi[64][72];
    const int s0 = blockIdx.x * 64;
    const int bh = blockIdx.y;
    const int tid = threadIdx.x;
    const int r = tid >> 2, cs = (tid & 3) * 16;
    const size_t sbase = ((size_t)bh * T_ + s0 + r) * 64 + cs;
    #pragma unroll
    for (int j = 0; j < 2; ++j)
        *(uint4*)&thi[r][cs + j*8] = *(const uint4*)(g_vhi + sbase + j*8);
    __syncthreads();
    const int d = tid >> 2, ss = (tid & 3) * 16;
    const size_t dbase = ((size_t)bh * 64 + d) * T_ + s0 + ss;
    #pragma unroll
    for (int j = 0; j < 2; ++j) {
        uint32_t ph[4];
        #pragma unroll
        for (int q = 0; q < 4; ++q) {
            int s = ss + j*8 + q*2;
            __half2 a; a.x = thi[s][d]; a.y = thi[s+1][d];
            ph[q] = *(uint32_t*)&a;
        }
        *(uint4*)(g_vthi + dbase + j*8) = *(uint4*)ph;
    }
}

// --------------------------- HMMA fused attention ----------------------------
// All operands single fp16. S: 1 MMA/step; PV: 1 MMA/step.
#define KSTR 144u
#define QSTR 144u
#define VTSTR 1040u
#define SM_K 0u            // 512*144 = 73728
#define SM_VT 0u           // 64*1040 = 66560 (overlays K)
#define SM_Q 73728u        // 9216
#define SM_OBUF 73728u     // 18432 (overlays Q after fragments in regs)
#define OSTRF 72
#define SM_EXM 92160u
#define SM_EXS 93184u
#define ATTN_SMEM 94208

__global__ void __launch_bounds__(512) attn_k(float* __restrict__ probs)
{
    extern __shared__ char smem[];
    const uint32_t sb = smem_u32(smem);
    const int tid = threadIdx.x;
    const int wid = tid >> 5, ln = tid & 31;
    const int wm = wid & 3, wq = wid >> 2;
    const int b = blockIdx.z, h = blockIdx.y, t0 = blockIdx.x * 64;
    const int bh = b * H_ + h;
    const int lr = ln >> 2, lc = ln & 3;

    // ---- load K (512 rows) + Q (64 rows) ----
    {
        const __half* khi = g_khi + (size_t)bh * T_ * 64;
        #pragma unroll
        for (int i = 0; i < 8; ++i) {
            int idx = tid + i * 512;
            int r = idx >> 3, sg = idx & 7;
            asm volatile("cp.async.cg.shared.global [%0], [%1], 16;"
                :: "r"(sb + SM_K + r*KSTR + sg*16), "l"(khi + (size_t)r*64 + sg*8));
        }
        const __half* qhi = g_qhi + ((size_t)bh * T_ + t0) * 64;
        {
            int r = tid >> 3, sg = tid & 7;
            asm volatile("cp.async.cg.shared.global [%0], [%1], 16;"
                :: "r"(sb + SM_Q + r*QSTR + sg*16), "l"(qhi + (size_t)r*64 + sg*8));
        }
        asm volatile("cp.async.commit_group;");
        asm volatile("cp.async.wait_group 0;");
    }
    __syncthreads();

    // ---- Q fragments ----
    uint32_t aH[4][4];
    {
        const int row = wm * 16 + lr;
        #pragma unroll
        for (int ks = 0; ks < 4; ++ks) {
            uint32_t off = row * QSTR + ks * 32 + lc * 4;
            aH[ks][0] = lds32(sb + SM_Q + off);
            aH[ks][1] = lds32(sb + SM_Q + off + 8*QSTR);
            aH[ks][2] = lds32(sb + SM_Q + off + 16);
            aH[ks][3] = lds32(sb + SM_Q + off + 8*QSTR + 16);
        }
    }

    // ---- S = Q K^T  (1 MMA per step) ----
    float acc[16][4];
    #pragma unroll
    for (int nt = 0; nt < 16; ++nt) { acc[nt][0]=acc[nt][1]=acc[nt][2]=acc[nt][3]=0.f; }
    #pragma unroll
    for (int nt = 0; nt < 16; ++nt) {
        uint32_t krow = (uint32_t)(wq * 128 + nt * 8 + lr);
        #pragma unroll
        for (int ks = 0; ks < 4; ++ks) {
            uint32_t boff = krow * KSTR + ks * 32 + lc * 4;
            uint32_t bh0 = lds32(sb + SM_K + boff);
            uint32_t bh1 = lds32(sb + SM_K + boff + 16);
            mma_f16(acc[nt], aH[ks], bh0, bh1);
        }
    }

    // ---- softmax over 512 keys ----
    const int row0 = wm * 16 + lr;
    {
        float mx0 = -1e30f, mx1 = -1e30f;
        #pragma unroll
        for (int nt = 0; nt < 16; ++nt) {
            mx0 = fmaxf(mx0, fmaxf(acc[nt][0], acc[nt][1]));
            mx1 = fmaxf(mx1, fmaxf(acc[nt][2], acc[nt][3]));
        }
        mx0 = fmaxf(mx0, __shfl_xor_sync(0xffffffffu, mx0, 1));
        mx0 = fmaxf(mx0, __shfl_xor_sync(0xffffffffu, mx0, 2));
        mx1 = fmaxf(mx1, __shfl_xor_sync(0xffffffffu, mx1, 1));
        mx1 = fmaxf(mx1, __shfl_xor_sync(0xffffffffu, mx1, 2));
        float* exm = (float*)(smem + SM_EXM);
        if (lc == 0) { exm[wq*64 + row0] = mx0; exm[wq*64 + row0 + 8] = mx1; }
        __syncthreads();     // all warps past S MMAs -> K region dead

        // ---- prefetch VT into K region ----
        {
            const __half* vthi = g_vthi + (size_t)bh * 64 * T_;
            #pragma unroll
            for (int i = 0; i < 8; ++i) {
                int idx = tid + i * 512;
                int d = idx >> 6, sg = idx & 63;
                asm volatile("cp.async.cg.shared.global [%0], [%1], 16;"
                    :: "r"(sb + SM_VT + d*VTSTR + sg*16), "l"(vthi + (size_t)d*T_ + sg*8));
            }
            asm volatile("cp.async.commit_group;");
        }

        float m0 = fmaxf(fmaxf(exm[row0],      exm[64+row0]),
                         fmaxf(exm[128+row0],  exm[192+row0]));
        float m1 = fmaxf(fmaxf(exm[row0+8],    exm[64+row0+8]),
                         fmaxf(exm[128+row0+8],exm[192+row0+8]));
        float s0 = 0.f, s1 = 0.f;
        #pragma unroll
        for (int nt = 0; nt < 16; ++nt) {
            acc[nt][0] = __expf(acc[nt][0] - m0); s0 += acc[nt][0];
            acc[nt][1] = __expf(acc[nt][1] - m0); s0 += acc[nt][1];
            acc[nt][2] = __expf(acc[nt][2] - m1); s1 += acc[nt][2];
            acc[nt][3] = __expf(acc[nt][3] - m1); s1 += acc[nt][3];
        }
        s0 += __shfl_xor_sync(0xffffffffu, s0, 1);
        s0 += __shfl_xor_sync(0xffffffffu, s0, 2);
        s1 += __shfl_xor_sync(0xffffffffu, s1, 1);
        s1 += __shfl_xor_sync(0xffffffffu, s1, 2);
        float* exs = (float*)(smem + SM_EXS);
        if (lc == 0) { exs[wq*64 + row0] = s0; exs[wq*64 + row0 + 8] = s1; }
        __syncthreads();
        float inv0 = 1.0f / (exs[row0] + exs[64+row0] + exs[128+row0] + exs[192+row0]);
        float inv1 = 1.0f / (exs[row0+8] + exs[64+row0+8] + exs[128+row0+8] + exs[192+row0+8]);
        #pragma unroll
        for (int nt = 0; nt < 16; ++nt) {
            acc[nt][0] *= inv0; acc[nt][1] *= inv0;
            acc[nt][2] *= inv1; acc[nt][3] *= inv1;
        }
    }

    // ---- wait VT, then PV with probs stores interleaved ----
    asm volatile("cp.async.wait_group 0;");
    __syncthreads();

    float* p0 = probs + ((size_t)bh * T_ + t0 + row0) * 512 + wq*128 + lc*2;
    float* p1 = p0 + (size_t)8 * 512;

    float oacc[8][4];
    #pragma unroll
    for (int dn = 0; dn < 8; ++dn) { oacc[dn][0]=oacc[dn][1]=oacc[dn][2]=oacc[dn][3]=0.f; }
    #pragma unroll
    for (int kk = 0; kk < 8; ++kk) {
        uint32_t phi[4];
        phi[0] = pack2h(acc[2*kk][0],   acc[2*kk][1]);
        phi[1] = pack2h(acc[2*kk][2],   acc[2*kk][3]);
        phi[2] = pack2h(acc[2*kk+1][0], acc[2*kk+1][1]);
        phi[3] = pack2h(acc[2*kk+1][2], acc[2*kk+1][3]);
        // interleaved probs stores (overlap STG with tensor work)
        {
            float2 v00 = {acc[2*kk][0],   acc[2*kk][1]};
            float2 v01 = {acc[2*kk][2],   acc[2*kk][3]};
            float2 v10 = {acc[2*kk+1][0], acc[2*kk+1][1]};
            float2 v11 = {acc[2*kk+1][2], acc[2*kk+1][3]};
            *(float2*)(p0 + (2*kk)*8)   = v00;
            *(float2*)(p1 + (2*kk)*8)   = v01;
            *(float2*)(p0 + (2*kk+1)*8) = v10;
            *(float2*)(p1 + (2*kk+1)*8) = v11;
        }
        uint32_t colV = (uint32_t)((wq*128 + kk*16 + lc*2) * 2);
        #pragma unroll
        for (int dn = 0; dn < 8; ++dn) {
            uint32_t vrow = (uint32_t)(dn*8 + lr);
            uint32_t offH = vrow * VTSTR + colV;
            uint32_t bh0 = lds32(sb + SM_VT + offH);
            uint32_t bh1 = lds32(sb + SM_VT + offH + 16);
            mma_f16(oacc[dn], phi, bh0, bh1);
        }
    }

    // ---- cross-warp reduce ----
    float* obuf = (float*)(smem + SM_OBUF);
    #pragma unroll
    for (int g = 0; g < 4; ++g) {
        if (wq == g) {
            #pragma unroll
            for (int dn = 0; dn < 8; ++dn) {
                int c = dn*8 + lc*2;
                float* b0 = obuf + row0 * OSTRF + c;
                float* b1 = obuf + (row0 + 8) * OSTRF + c;
                if (g == 0) {
                    b0[0] = oacc[dn][0]; b0[1] = oacc[dn][1];
                    b1[0] = oacc[dn][2]; b1[1] = oacc[dn][3];
                } else {
                    b0[0] += oacc[dn][0]; b0[1] += oacc[dn][1];
                    b1[0] += oacc[dn][2]; b1[1] += oacc[dn][3];
                }
            }
        }
        __syncthreads();
    }

    // ---- write O as hi-only 8B granules for OUT gemm ----
    {
        int row = tid >> 3, s2 = tid & 7;
        const float* src = obuf + row * OSTRF;
        size_t rb = ((size_t)b * T_ + t0 + row) * 1536 + (size_t)h * 128;
        #pragma unroll
        for (int u = 0; u < 2; ++u) {
            int s = s2 * 2 + u;
            int g = s >> 2, lcx = s & 3;
            int k0 = g * 16 + lcx * 2;
            uint32_t w[2];
            pack_g8(src[k0], src[k0+1], src[k0+8], src[k0+9], w);
            *(uint2*)(g_oh + rb + g*32 + lcx*8) = *(uint2*)w;
        }
    }
}

// --------------------------------- launcher ---------------------------------
extern "C" void kernel_launch(void* const* d_in, const int* in_sizes, int n_in,
                              void* d_out, int out_size)
{
    const float* x     = (const float*)d_in[0];
    const float* Wqkv  = (const float*)d_in[1];
    const float* bqkv  = (const float*)d_in[2];
    const float* Wph   = (const float*)d_in[3];
    const float* bph   = (const float*)d_in[4];
    const float* Wproj = (const float*)d_in[5];
    const float* bproj = (const float*)d_in[6];
    float* out = (float*)d_out;
    float* sa_out = out;
    float* probs  = out + (size_t)BT_*C_;

    uint8_t *xh_p, *wqh_p, *oh_p, *wch_p;
    float *wcomb_p, *bcomb_p;
    cudaGetSymbolAddress((void**)&xh_p,   g_xh);
    cudaGetSymbolAddress((void**)&wqh_p,  g_wqh);
    cudaGetSymbolAddress((void**)&oh_p,   g_oh);
    cudaGetSymbolAddress((void**)&wch_p,  g_wch);
    cudaGetSymbolAddress((void**)&wcomb_p, g_wcomb);
    cudaGetSymbolAddress((void**)&bcomb_p, g_bcomb);

    static int attrs_set = 0;
    if (!attrs_set) {
        cudaFuncSetAttribute(hmma_gemm<0>, cudaFuncAttributeMaxDynamicSharedMemorySize, HM_SMEM);
        cudaFuncSetAttribute(hmma_gemm<1>, cudaFuncAttributeMaxDynamicSharedMemorySize, HM_SMEM);
        cudaFuncSetAttribute(attn_k, cudaFuncAttributeMaxDynamicSharedMemorySize, ATTN_SMEM);
        attrs_set = 1;
    }

    // 1-3: prep on QKV critical path (+ wcomb zero / bcomb init)
    k_prep_xh<<<BT_*192/256, 256>>>(x);
    k_prep_wqh<<<NQKV_*192/256, 256>>>(Wqkv);
    k_binit<<<(C_*C_ + C_ + 255)/256, 256>>>(bproj);

    // 4: QKV GEMM (profiled slot) -> q/k/v fp16
    hmma_gemm<1><<<dim3(NQKV_/128, BT_/128), 128, HM_SMEM>>>(
        xh_p, wqh_p, nullptr, bqkv);

    // 5-7: Wcomb chain (independent of attention)
    k_bcomb<<<288, 256>>>(bph, Wproj);
    sgemm64ks<<<dim3(4, 12, 12), 256>>>(Wph, Wproj, wcomb_p);
    k_prep_wch<<<C_*192/256, 256>>>();

    // 8: V transpose
    k_vT<<<dim3(T_/64, B_*H_), 256>>>();

    // 9: fused attention -> probs + O(hi granules)
    attn_k<<<dim3(T_/64, H_, B_), 512, ATTN_SMEM>>>(probs);

    // 10: output GEMM + bcomb -> sa_out
    hmma_gemm<0><<<dim3(C_/128, BT_/128), 128, HM_SMEM>>>(
        oh_p, wch_p, sa_out, bcomb_p);
}